// round 3
// baseline (speedup 1.0000x reference)
#include <cuda_runtime.h>
#include <cstddef>

#define NMAX 100000
#define EMAX 1700000
#define D 128

typedef unsigned long long ull;

// Scratch (device-global, allocation-free per harness rules)
__device__ float g_agg[(size_t)NMAX * D];
__device__ float g_h1[(size_t)NMAX * D];
__device__ float g_h2[(size_t)NMAX * D];
__device__ int   g_deg[NMAX];
__device__ int   g_off[NMAX + 1];
__device__ int   g_cursor[NMAX];
__device__ int   g_nbr[EMAX];
__device__ int   g_aux[1024];

// ---- packed f32x2 helpers (FFMA2 path, exact fp32) ----
__device__ __forceinline__ ull pack2(float lo, float hi) {
    ull r;
    asm("mov.b64 %0, {%1, %2};" : "=l"(r) : "f"(lo), "f"(hi));
    return r;
}
__device__ __forceinline__ void fma2(ull& acc, ull a, ull b) {
    asm("fma.rn.f32x2 %0, %1, %2, %0;" : "+l"(acc) : "l"(a), "l"(b));
}
__device__ __forceinline__ float2 unpack2(ull v) {
    float lo, hi;
    asm("mov.b64 {%0, %1}, %2;" : "=f"(lo), "=f"(hi) : "l"(v));
    return make_float2(lo, hi);
}

// ---------------------------------------------------------------------------
// CSR build
// ---------------------------------------------------------------------------
__global__ void zero_deg_kernel(int n) {
    int i = blockIdx.x * blockDim.x + threadIdx.x;
    int stride = gridDim.x * blockDim.x;
    for (int j = i; j < n; j += stride) g_deg[j] = 0;
}

__global__ void __launch_bounds__(256) count_kernel(const int* __restrict__ ei, int E) {
    int e = blockIdx.x * 256 + threadIdx.x;
    if (e >= E) return;
    atomicAdd(&g_deg[__ldg(ei + E + e)], 1);
}

__global__ void __launch_bounds__(1024) scan1_kernel(int n) {
    __shared__ int s[1024];
    int t = threadIdx.x;
    int i = blockIdx.x * 1024 + t;
    int v = (i < n) ? g_deg[i] : 0;
    s[t] = v;
    __syncthreads();
#pragma unroll
    for (int d = 1; d < 1024; d <<= 1) {
        int add = (t >= d) ? s[t - d] : 0;
        __syncthreads();
        s[t] += add;
        __syncthreads();
    }
    if (i < n) g_off[i] = s[t] - v;
    if (t == 1023) g_aux[blockIdx.x] = s[1023];
}

__global__ void __launch_bounds__(1024) scan2_kernel(int nb) {
    __shared__ int s[1024];
    int t = threadIdx.x;
    int v = (t < nb) ? g_aux[t] : 0;
    s[t] = v;
    __syncthreads();
#pragma unroll
    for (int d = 1; d < 1024; d <<= 1) {
        int add = (t >= d) ? s[t - d] : 0;
        __syncthreads();
        s[t] += add;
        __syncthreads();
    }
    if (t < nb) g_aux[t] = s[t] - v;
}

__global__ void __launch_bounds__(256) scan3_kernel(int n) {
    int i = blockIdx.x * 256 + threadIdx.x;
    if (i >= n) return;
    int o = g_off[i] + g_aux[i >> 10];
    g_off[i] = o;
    g_cursor[i] = o;
}

__global__ void __launch_bounds__(256) fill_kernel(const int* __restrict__ ei, int E) {
    int e = blockIdx.x * 256 + threadIdx.x;
    if (e >= E) return;
    int s = __ldg(ei + e);
    int d = __ldg(ei + E + e);
    int pos = atomicAdd(&g_cursor[d], 1);
    g_nbr[pos] = s;
}

// ---------------------------------------------------------------------------
// Gather-mean: warp per node
// ---------------------------------------------------------------------------
__global__ void __launch_bounds__(256) gather_kernel(const float* __restrict__ feat, int n) {
    int v = (blockIdx.x * 256 + threadIdx.x) >> 5;
    int lane = threadIdx.x & 31;
    if (v >= n) return;
    int start = g_off[v];
    int deg = g_deg[v];
    const float4* f4 = reinterpret_cast<const float4*>(feat);
    float4 acc = make_float4(0.f, 0.f, 0.f, 0.f);
    int i = 0;
    for (; i + 4 <= deg; i += 4) {
        int s0 = __ldg(g_nbr + start + i);
        int s1 = __ldg(g_nbr + start + i + 1);
        int s2 = __ldg(g_nbr + start + i + 2);
        int s3 = __ldg(g_nbr + start + i + 3);
        float4 a = __ldg(f4 + (size_t)s0 * 32 + lane);
        float4 b = __ldg(f4 + (size_t)s1 * 32 + lane);
        float4 c = __ldg(f4 + (size_t)s2 * 32 + lane);
        float4 d = __ldg(f4 + (size_t)s3 * 32 + lane);
        acc.x += (a.x + b.x) + (c.x + d.x);
        acc.y += (a.y + b.y) + (c.y + d.y);
        acc.z += (a.z + b.z) + (c.z + d.z);
        acc.w += (a.w + b.w) + (c.w + d.w);
    }
    for (; i < deg; i++) {
        int s0 = __ldg(g_nbr + start + i);
        float4 a = __ldg(f4 + (size_t)s0 * 32 + lane);
        acc.x += a.x; acc.y += a.y; acc.z += a.z; acc.w += a.w;
    }
    float inv = 1.0f / (float)max(deg, 1);
    acc.x *= inv; acc.y *= inv; acc.z *= inv; acc.w *= inv;
    reinterpret_cast<float4*>(g_agg)[(size_t)v * 32 + lane] = acc;
}

// ---------------------------------------------------------------------------
// Fused SAGE layer with packed f32x2 FMA:
// out = relu(agg @ wl + xin @ wr + bias)
// Block 256, tile 64 rows. Thread: 4 row-pairs x 4 cols, packed accumulators.
// ---------------------------------------------------------------------------
__global__ void __launch_bounds__(256) layer_kernel(
    const float* __restrict__ xin,
    const float* __restrict__ wl, const float* __restrict__ wr,
    const float* __restrict__ bias, float* __restrict__ out, int n)
{
    extern __shared__ float smem[];
    float* s_wl = smem;                 // 128x128, k-major: [k*128 + c]
    float* s_wr = smem + 16384;
    float* s_a  = smem + 32768;         // 64x128 row-major
    float* s_x  = smem + 40960;

    int tid = threadIdx.x;

    const float4* wl4 = reinterpret_cast<const float4*>(wl);
    const float4* wr4 = reinterpret_cast<const float4*>(wr);
    float4* s_wl4 = reinterpret_cast<float4*>(s_wl);
    float4* s_wr4 = reinterpret_cast<float4*>(s_wr);
#pragma unroll
    for (int i = 0; i < 16; i++) {
        s_wl4[tid + i * 256] = __ldg(wl4 + tid + i * 256);
        s_wr4[tid + i * 256] = __ldg(wr4 + tid + i * 256);
    }

    int r0 = blockIdx.x * 64;
    const float4* agg4 = reinterpret_cast<const float4*>(g_agg);
    const float4* x4   = reinterpret_cast<const float4*>(xin);
    float4* s_a4 = reinterpret_cast<float4*>(s_a);
    float4* s_x4 = reinterpret_cast<float4*>(s_x);
#pragma unroll
    for (int i = 0; i < 8; i++) {
        int f   = tid + i * 256;   // 64 rows * 32 float4
        int row = f >> 5;
        int c4  = f & 31;
        int gr  = r0 + row;
        if (gr >= n) gr = n - 1;
        s_a4[f] = agg4[(size_t)gr * 32 + c4];
        s_x4[f] = x4[(size_t)gr * 32 + c4];
    }
    __syncthreads();

    int lane = tid & 31;   // cols lane*4 .. lane*4+3
    int wy   = tid >> 5;   // rows wy*8 .. wy*8+7  (4 row-pairs)
    int rbase = wy * 8;

    ull acc[4][4];
#pragma unroll
    for (int j = 0; j < 4; j++)
#pragma unroll
        for (int c = 0; c < 4; c++) acc[j][c] = 0ull;

#pragma unroll 2
    for (int k = 0; k < 128; k++) {
        float4 wlv = s_wl4[k * 32 + lane];
        float4 wrv = s_wr4[k * 32 + lane];
        ull wl2[4], wr2[4];
        wl2[0] = pack2(wlv.x, wlv.x); wl2[1] = pack2(wlv.y, wlv.y);
        wl2[2] = pack2(wlv.z, wlv.z); wl2[3] = pack2(wlv.w, wlv.w);
        wr2[0] = pack2(wrv.x, wrv.x); wr2[1] = pack2(wrv.y, wrv.y);
        wr2[2] = pack2(wrv.z, wrv.z); wr2[3] = pack2(wrv.w, wrv.w);
#pragma unroll
        for (int j = 0; j < 4; j++) {
            int r = rbase + 2 * j;
            ull a2 = pack2(s_a[r * 128 + k], s_a[(r + 1) * 128 + k]);
            ull x2 = pack2(s_x[r * 128 + k], s_x[(r + 1) * 128 + k]);
            fma2(acc[j][0], a2, wl2[0]); fma2(acc[j][0], x2, wr2[0]);
            fma2(acc[j][1], a2, wl2[1]); fma2(acc[j][1], x2, wr2[1]);
            fma2(acc[j][2], a2, wl2[2]); fma2(acc[j][2], x2, wr2[2]);
            fma2(acc[j][3], a2, wl2[3]); fma2(acc[j][3], x2, wr2[3]);
        }
    }

    float4 bv = __ldg(reinterpret_cast<const float4*>(bias) + lane);
#pragma unroll
    for (int j = 0; j < 4; j++) {
        float2 u0 = unpack2(acc[j][0]);
        float2 u1 = unpack2(acc[j][1]);
        float2 u2 = unpack2(acc[j][2]);
        float2 u3 = unpack2(acc[j][3]);
        int gr = r0 + rbase + 2 * j;
        if (gr < n) {
            float4 o;
            o.x = fmaxf(u0.x + bv.x, 0.f);
            o.y = fmaxf(u1.x + bv.y, 0.f);
            o.z = fmaxf(u2.x + bv.z, 0.f);
            o.w = fmaxf(u3.x + bv.w, 0.f);
            reinterpret_cast<float4*>(out)[(size_t)gr * 32 + lane] = o;
        }
        if (gr + 1 < n) {
            float4 o;
            o.x = fmaxf(u0.y + bv.x, 0.f);
            o.y = fmaxf(u1.y + bv.y, 0.f);
            o.z = fmaxf(u2.y + bv.z, 0.f);
            o.w = fmaxf(u3.y + bv.w, 0.f);
            reinterpret_cast<float4*>(out)[(size_t)(gr + 1) * 32 + lane] = o;
        }
    }
}

// ---------------------------------------------------------------------------
// Output head: out[row] = [h1[row], h2[row]] @ w_out + b_out   (K=256, Ncls=40)
// Block 256: 128 rows/block. Thread: 2 row-pairs x 5 cols, packed f32x2.
// ---------------------------------------------------------------------------
__global__ void __launch_bounds__(256) out_kernel(
    const float* __restrict__ w_out, const float* __restrict__ b_out,
    float* __restrict__ out, int n)
{
    extern __shared__ float sm[];
    float* ws = sm;                 // 256*40 = 10240 floats
    float* hs = sm + 10240;         // 128 rows * 257 floats (padded)

    int tid = threadIdx.x;
    const float4* w4 = reinterpret_cast<const float4*>(w_out);
    float4* ws4 = reinterpret_cast<float4*>(ws);
#pragma unroll
    for (int i = 0; i < 10; i++) ws4[tid + i * 256] = __ldg(w4 + tid + i * 256);

    int r0 = blockIdx.x * 128;
#pragma unroll
    for (int i = 0; i < 32; i++) {
        int f = tid + i * 256;          // 128 rows * 64 float4
        int row = f >> 6;
        int w = f & 63;
        int gr = r0 + row;
        if (gr >= n) gr = n - 1;
        float4 v = (w < 32)
            ? reinterpret_cast<const float4*>(g_h1)[(size_t)gr * 32 + w]
            : reinterpret_cast<const float4*>(g_h2)[(size_t)gr * 32 + (w - 32)];
        float* dst = hs + row * 257 + w * 4;
        dst[0] = v.x; dst[1] = v.y; dst[2] = v.z; dst[3] = v.w;
    }
    __syncthreads();

    int cg = tid & 7;      // cols cg*5 .. cg*5+4
    int rq = tid >> 3;     // rows rq*4 .. rq*4+3  (2 row-pairs)
    int cbase = cg * 5;
    const float* hrow = hs + (rq * 4) * 257;

    ull acc[2][5];
#pragma unroll
    for (int j = 0; j < 2; j++)
#pragma unroll
        for (int c = 0; c < 5; c++) acc[j][c] = 0ull;

#pragma unroll 4
    for (int k = 0; k < 256; k++) {
        ull wp[5];
#pragma unroll
        for (int c = 0; c < 5; c++) {
            float w = ws[k * 40 + cbase + c];
            wp[c] = pack2(w, w);
        }
        ull h01 = pack2(hrow[k], hrow[257 + k]);
        ull h23 = pack2(hrow[2 * 257 + k], hrow[3 * 257 + k]);
#pragma unroll
        for (int c = 0; c < 5; c++) {
            fma2(acc[0][c], h01, wp[c]);
            fma2(acc[1][c], h23, wp[c]);
        }
    }

#pragma unroll
    for (int j = 0; j < 2; j++) {
#pragma unroll
        for (int c = 0; c < 5; c++) {
            float2 u = unpack2(acc[j][c]);
            float bb = __ldg(b_out + cbase + c);
            int gr0 = r0 + rq * 4 + 2 * j;
            if (gr0 < n)     out[(size_t)gr0 * 40 + cbase + c] = u.x + bb;
            if (gr0 + 1 < n) out[(size_t)(gr0 + 1) * 40 + cbase + c] = u.y + bb;
        }
    }
}

// ---------------------------------------------------------------------------
static void build_csr_and_gather(const int* ei, int E, const float* feat, int n)
{
    int nb_scan = (n + 1023) / 1024;
    zero_deg_kernel<<<256, 256>>>(n);
    count_kernel<<<(E + 255) / 256, 256>>>(ei, E);
    scan1_kernel<<<nb_scan, 1024>>>(n);
    scan2_kernel<<<1, 1024>>>(nb_scan);
    scan3_kernel<<<(n + 255) / 256, 256>>>(n);
    fill_kernel<<<(E + 255) / 256, 256>>>(ei, E);
    gather_kernel<<<(n * 32 + 255) / 256, 256>>>(feat, n);
}

extern "C" void kernel_launch(void* const* d_in, const int* in_sizes, int n_in,
                              void* d_out, int out_size)
{
    const float* x     = (const float*)d_in[0];
    const int*   ei1   = (const int*)d_in[1];
    const int*   ei2   = (const int*)d_in[2];
    const float* wl1   = (const float*)d_in[3];
    const float* wr1   = (const float*)d_in[4];
    const float* b1    = (const float*)d_in[5];
    const float* wl2   = (const float*)d_in[6];
    const float* wr2   = (const float*)d_in[7];
    const float* b2    = (const float*)d_in[8];
    const float* w_out = (const float*)d_in[9];
    const float* b_out = (const float*)d_in[10];

    int n  = in_sizes[0] / D;
    int E1 = in_sizes[1] / 2;
    int E2 = in_sizes[2] / 2;
    int n_rows_out = out_size / 40;

    void *p_h1 = nullptr, *p_h2 = nullptr;
    cudaGetSymbolAddress(&p_h1, g_h1);
    cudaGetSymbolAddress(&p_h2, g_h2);
    float* h1 = (float*)p_h1;
    float* h2 = (float*)p_h2;

    cudaFuncSetAttribute(layer_kernel,
                         cudaFuncAttributeMaxDynamicSharedMemorySize, 196608);
    cudaFuncSetAttribute(out_kernel,
                         cudaFuncAttributeMaxDynamicSharedMemorySize, 172544);

    int layer_blocks = (n + 63) / 64;

    // ---- layer 1 ----
    build_csr_and_gather(ei1, E1, x, n);
    layer_kernel<<<layer_blocks, 256, 196608>>>(x, wl1, wr1, b1, h1, n);

    // ---- layer 2 ----
    build_csr_and_gather(ei2, E2, h1, n);
    layer_kernel<<<layer_blocks, 256, 196608>>>(h1, wl2, wr2, b2, h2, n);

    // ---- JK cat + linear head ----
    out_kernel<<<(n_rows_out + 127) / 128, 256, 172544>>>(
        w_out, b_out, (float*)d_out, n_rows_out);
}

// round 5
// speedup vs baseline: 1.5442x; 1.5442x over previous
#include <cuda_runtime.h>
#include <cuda_bf16.h>
#include <cstddef>
#include <cstdint>

#define NMAX 100000
#define EMAX 1700000
#define D 128
#define APAD 132   // padded bf16 row stride in smem

// ---------------------------------------------------------------------------
// Scratch (device-global, allocation-free per harness rules)
// ---------------------------------------------------------------------------
__device__ float g_agg[(size_t)NMAX * D];
__device__ float g_h1[(size_t)NMAX * D];
__device__ float g_h2[(size_t)NMAX * D];
__device__ int   g_deg[NMAX];
__device__ int   g_off[NMAX + 1];
__device__ int   g_cursor[NMAX];
__device__ int   g_nbr[EMAX];
__device__ int   g_aux[1024];
// Transposed bf16 hi/lo weight images: [chunk][n_outcol][k], chunk 0=wl 1=wr
__device__ unsigned short g_wth[2 * 128 * 128];
__device__ unsigned short g_wtl[2 * 128 * 128];

__device__ __forceinline__ unsigned short bfu(__nv_bfloat16 b) {
    return __bfloat16_as_ushort(b);
}

// mma.sync m16n8k16 bf16 (plain-target PTX; HMMA in SASS)
__device__ __forceinline__ void mma16816(float* c, const unsigned* a, const unsigned* b) {
    asm volatile(
        "mma.sync.aligned.m16n8k16.row.col.f32.bf16.bf16.f32 "
        "{%0,%1,%2,%3}, {%4,%5,%6,%7}, {%8,%9}, {%0,%1,%2,%3};"
        : "+f"(c[0]), "+f"(c[1]), "+f"(c[2]), "+f"(c[3])
        : "r"(a[0]), "r"(a[1]), "r"(a[2]), "r"(a[3]), "r"(b[0]), "r"(b[1]));
}

// ---------------------------------------------------------------------------
// CSR build (unchanged)
// ---------------------------------------------------------------------------
__global__ void zero_deg_kernel(int n) {
    int i = blockIdx.x * blockDim.x + threadIdx.x;
    int stride = gridDim.x * blockDim.x;
    for (int j = i; j < n; j += stride) g_deg[j] = 0;
}

__global__ void __launch_bounds__(256) count_kernel(const int* __restrict__ ei, int E) {
    int e = blockIdx.x * 256 + threadIdx.x;
    if (e >= E) return;
    atomicAdd(&g_deg[__ldg(ei + E + e)], 1);
}

__global__ void __launch_bounds__(1024) scan1_kernel(int n) {
    __shared__ int s[1024];
    int t = threadIdx.x;
    int i = blockIdx.x * 1024 + t;
    int v = (i < n) ? g_deg[i] : 0;
    s[t] = v;
    __syncthreads();
#pragma unroll
    for (int d = 1; d < 1024; d <<= 1) {
        int add = (t >= d) ? s[t - d] : 0;
        __syncthreads();
        s[t] += add;
        __syncthreads();
    }
    if (i < n) g_off[i] = s[t] - v;
    if (t == 1023) g_aux[blockIdx.x] = s[1023];
}

__global__ void __launch_bounds__(1024) scan2_kernel(int nb) {
    __shared__ int s[1024];
    int t = threadIdx.x;
    int v = (t < nb) ? g_aux[t] : 0;
    s[t] = v;
    __syncthreads();
#pragma unroll
    for (int d = 1; d < 1024; d <<= 1) {
        int add = (t >= d) ? s[t - d] : 0;
        __syncthreads();
        s[t] += add;
        __syncthreads();
    }
    if (t < nb) g_aux[t] = s[t] - v;
}

__global__ void __launch_bounds__(256) scan3_kernel(int n) {
    int i = blockIdx.x * 256 + threadIdx.x;
    if (i >= n) return;
    int o = g_off[i] + g_aux[i >> 10];
    g_off[i] = o;
    g_cursor[i] = o;
}

__global__ void __launch_bounds__(256) fill_kernel(const int* __restrict__ ei, int E) {
    int e = blockIdx.x * 256 + threadIdx.x;
    if (e >= E) return;
    int s = __ldg(ei + e);
    int d = __ldg(ei + E + e);
    int pos = atomicAdd(&g_cursor[d], 1);
    g_nbr[pos] = s;
}

// ---------------------------------------------------------------------------
// Gather-mean: warp per node (unchanged)
// ---------------------------------------------------------------------------
__global__ void __launch_bounds__(256) gather_kernel(const float* __restrict__ feat, int n) {
    int v = (blockIdx.x * 256 + threadIdx.x) >> 5;
    int lane = threadIdx.x & 31;
    if (v >= n) return;
    int start = g_off[v];
    int deg = g_deg[v];
    const float4* f4 = reinterpret_cast<const float4*>(feat);
    float4 acc = make_float4(0.f, 0.f, 0.f, 0.f);
    int i = 0;
    for (; i + 4 <= deg; i += 4) {
        int s0 = __ldg(g_nbr + start + i);
        int s1 = __ldg(g_nbr + start + i + 1);
        int s2 = __ldg(g_nbr + start + i + 2);
        int s3 = __ldg(g_nbr + start + i + 3);
        float4 a = __ldg(f4 + (size_t)s0 * 32 + lane);
        float4 b = __ldg(f4 + (size_t)s1 * 32 + lane);
        float4 c = __ldg(f4 + (size_t)s2 * 32 + lane);
        float4 d = __ldg(f4 + (size_t)s3 * 32 + lane);
        acc.x += (a.x + b.x) + (c.x + d.x);
        acc.y += (a.y + b.y) + (c.y + d.y);
        acc.z += (a.z + b.z) + (c.z + d.z);
        acc.w += (a.w + b.w) + (c.w + d.w);
    }
    for (; i < deg; i++) {
        int s0 = __ldg(g_nbr + start + i);
        float4 a = __ldg(f4 + (size_t)s0 * 32 + lane);
        acc.x += a.x; acc.y += a.y; acc.z += a.z; acc.w += a.w;
    }
    float inv = 1.0f / (float)max(deg, 1);
    acc.x *= inv; acc.y *= inv; acc.z *= inv; acc.w *= inv;
    reinterpret_cast<float4*>(g_agg)[(size_t)v * 32 + lane] = acc;
}

// ---------------------------------------------------------------------------
// Weight prep: split wl/wr into bf16 hi + bf16 residual, transpose to
// [n_outcol][k] (B column-major for mma.row.col). chunk 0=wl, 1=wr.
// ---------------------------------------------------------------------------
__global__ void __launch_bounds__(256) prep_w_kernel(const float* __restrict__ wl,
                                                     const float* __restrict__ wr) {
    int idx = blockIdx.x * 256 + threadIdx.x;   // 2*128*128 = 32768
    if (idx >= 32768) return;
    int c    = idx >> 14;
    int rem  = idx & 16383;
    int nrow = rem >> 7;     // output column
    int k    = rem & 127;
    const float* w = c ? wr : wl;
    float v = __ldg(w + k * 128 + nrow);
    __nv_bfloat16 hb = __float2bfloat16(v);
    __nv_bfloat16 lb = __float2bfloat16(v - __bfloat162float(hb));
    g_wth[idx] = bfu(hb);
    g_wtl[idx] = bfu(lb);
}

// ---------------------------------------------------------------------------
// HMMA SAGE layer: out = relu(agg @ wl + xin @ wr + bias)
// CTA: 64 rows x 128 cols. 8 warps = 2(M) x 4(N); warp tile 32x32.
// bf16 2-term split, 3 products, fp32 accumulate.
// SMEM: A hi/lo 64x132, W hi/lo 128x132 (bf16) = 101376 B -> 2 CTA/SM.
// ---------------------------------------------------------------------------
__global__ void __launch_bounds__(256) layer_mma_kernel(
    const float* __restrict__ xin, const float* __restrict__ bias,
    float* __restrict__ out, int n)
{
    extern __shared__ unsigned short sm[];
    unsigned short* s_ah = sm;                       // 64 x APAD
    unsigned short* s_al = sm + 64 * APAD;
    unsigned short* s_wh = sm + 2 * 64 * APAD;       // 128 x APAD
    unsigned short* s_wl = s_wh + 128 * APAD;

    int tid = threadIdx.x, wid = tid >> 5, lane = tid & 31;
    int r0 = blockIdx.x * 64;
    int mrow = (wid & 1) * 32;      // warp M origin within tile
    int ncol = (wid >> 1) * 32;     // warp N origin

    float acc[2][4][4];
#pragma unroll
    for (int mt = 0; mt < 2; mt++)
#pragma unroll
        for (int nt = 0; nt < 4; nt++)
#pragma unroll
            for (int q = 0; q < 4; q++) acc[mt][nt][q] = 0.f;

    for (int chunk = 0; chunk < 2; chunk++) {
        if (chunk) __syncthreads();   // protect smem reuse

        // ---- stage A (64 rows), fp32 -> bf16 hi/lo split ----
        const float4* src = (chunk == 0) ? reinterpret_cast<const float4*>(g_agg)
                                         : reinterpret_cast<const float4*>(xin);
#pragma unroll
        for (int i = 0; i < 8; i++) {
            int f = tid + i * 256;          // 64 rows * 32 float4
            int row = f >> 5, k4 = f & 31;
            int gr = r0 + row;
            if (gr >= n) gr = n - 1;
            float4 v = __ldg(src + (size_t)gr * 32 + k4);
            __nv_bfloat16 h0 = __float2bfloat16(v.x);
            __nv_bfloat16 h1 = __float2bfloat16(v.y);
            __nv_bfloat16 h2 = __float2bfloat16(v.z);
            __nv_bfloat16 h3 = __float2bfloat16(v.w);
            __nv_bfloat16 l0 = __float2bfloat16(v.x - __bfloat162float(h0));
            __nv_bfloat16 l1 = __float2bfloat16(v.y - __bfloat162float(h1));
            __nv_bfloat16 l2 = __float2bfloat16(v.z - __bfloat162float(h2));
            __nv_bfloat16 l3 = __float2bfloat16(v.w - __bfloat162float(h3));
            unsigned hp0 = (unsigned)bfu(h0) | ((unsigned)bfu(h1) << 16);
            unsigned hp1 = (unsigned)bfu(h2) | ((unsigned)bfu(h3) << 16);
            unsigned lp0 = (unsigned)bfu(l0) | ((unsigned)bfu(l1) << 16);
            unsigned lp1 = (unsigned)bfu(l2) | ((unsigned)bfu(l3) << 16);
            int off = row * APAD + k4 * 4;   // ushort index, 8B aligned
            *reinterpret_cast<uint2*>(s_ah + off) = make_uint2(hp0, hp1);
            *reinterpret_cast<uint2*>(s_al + off) = make_uint2(lp0, lp1);
        }

        // ---- stage W chunk (transposed images) ----
        {
            const uint2* gh = reinterpret_cast<const uint2*>(g_wth) + chunk * 4096;
            const uint2* gl = reinterpret_cast<const uint2*>(g_wtl) + chunk * 4096;
#pragma unroll
            for (int i = 0; i < 16; i++) {
                int j = tid + i * 256;        // 0..4095 = 128 rows * 32 uint2
                int nrow = j >> 5, kk = (j & 31) * 4;
                int off = nrow * APAD + kk;
                *reinterpret_cast<uint2*>(s_wh + off) = __ldg(gh + j);
                *reinterpret_cast<uint2*>(s_wl + off) = __ldg(gl + j);
            }
        }
        __syncthreads();

        // ---- compute: 8 k-steps of m16n8k16 ----
#pragma unroll
        for (int s = 0; s < 8; s++) {
            int k0 = s * 16;
            int kc = k0 + (lane & 3) * 2;
            // B fragments for 4 N tiles (hi and lo)
            unsigned bh[4][2], bl[4][2];
#pragma unroll
            for (int nt = 0; nt < 4; nt++) {
                int nn = ncol + nt * 8 + (lane >> 2);
                bh[nt][0] = *reinterpret_cast<unsigned*>(s_wh + nn * APAD + kc);
                bh[nt][1] = *reinterpret_cast<unsigned*>(s_wh + nn * APAD + kc + 8);
                bl[nt][0] = *reinterpret_cast<unsigned*>(s_wl + nn * APAD + kc);
                bl[nt][1] = *reinterpret_cast<unsigned*>(s_wl + nn * APAD + kc + 8);
            }
#pragma unroll
            for (int mt = 0; mt < 2; mt++) {
                int rr = mrow + mt * 16 + (lane >> 2);
                unsigned ah[4], al[4];
                ah[0] = *reinterpret_cast<unsigned*>(s_ah + rr * APAD + kc);
                ah[1] = *reinterpret_cast<unsigned*>(s_ah + (rr + 8) * APAD + kc);
                ah[2] = *reinterpret_cast<unsigned*>(s_ah + rr * APAD + kc + 8);
                ah[3] = *reinterpret_cast<unsigned*>(s_ah + (rr + 8) * APAD + kc + 8);
                al[0] = *reinterpret_cast<unsigned*>(s_al + rr * APAD + kc);
                al[1] = *reinterpret_cast<unsigned*>(s_al + (rr + 8) * APAD + kc);
                al[2] = *reinterpret_cast<unsigned*>(s_al + rr * APAD + kc + 8);
                al[3] = *reinterpret_cast<unsigned*>(s_al + (rr + 8) * APAD + kc + 8);
#pragma unroll
                for (int nt = 0; nt < 4; nt++) {
                    mma16816(acc[mt][nt], ah, bh[nt]);   // hi*hi
                    mma16816(acc[mt][nt], ah, bl[nt]);   // hi*lo
                    mma16816(acc[mt][nt], al, bh[nt]);   // lo*hi
                }
            }
        }
    }

    // ---- epilogue: bias + relu + store ----
#pragma unroll
    for (int mt = 0; mt < 2; mt++) {
#pragma unroll
        for (int nt = 0; nt < 4; nt++) {
            int col = ncol + nt * 8 + (lane & 3) * 2;
            float bx = __ldg(bias + col), by = __ldg(bias + col + 1);
            int row = r0 + mrow + mt * 16 + (lane >> 2);
            if (row < n) {
                float2 o;
                o.x = fmaxf(acc[mt][nt][0] + bx, 0.f);
                o.y = fmaxf(acc[mt][nt][1] + by, 0.f);
                *reinterpret_cast<float2*>(out + (size_t)row * 128 + col) = o;
            }
            if (row + 8 < n) {
                float2 o;
                o.x = fmaxf(acc[mt][nt][2] + bx, 0.f);
                o.y = fmaxf(acc[mt][nt][3] + by, 0.f);
                *reinterpret_cast<float2*>(out + (size_t)(row + 8) * 128 + col) = o;
            }
        }
    }
}

// ---------------------------------------------------------------------------
// Output head: out[row] = [h1,h2] @ w_out + b_out (K=256, Ncls=40)
// ---------------------------------------------------------------------------
__global__ void __launch_bounds__(256) out_kernel(
    const float* __restrict__ w_out, const float* __restrict__ b_out,
    float* __restrict__ out, int n)
{
    extern __shared__ float smf[];
    float* ws = smf;                // 256*40
    float* hs = smf + 10240;        // 128 rows * 257 (padded)

    int tid = threadIdx.x;
    const float4* w4 = reinterpret_cast<const float4*>(w_out);
    float4* ws4 = reinterpret_cast<float4*>(ws);
#pragma unroll
    for (int i = 0; i < 10; i++) ws4[tid + i * 256] = __ldg(w4 + tid + i * 256);

    int r0 = blockIdx.x * 128;
#pragma unroll
    for (int i = 0; i < 32; i++) {
        int f = tid + i * 256;
        int row = f >> 6;
        int w = f & 63;
        int gr = r0 + row;
        if (gr >= n) gr = n - 1;
        float4 v = (w < 32)
            ? reinterpret_cast<const float4*>(g_h1)[(size_t)gr * 32 + w]
            : reinterpret_cast<const float4*>(g_h2)[(size_t)gr * 32 + (w - 32)];
        float* dst = hs + row * 257 + w * 4;
        dst[0] = v.x; dst[1] = v.y; dst[2] = v.z; dst[3] = v.w;
    }
    __syncthreads();

    int cg = tid & 7;
    int rq = tid >> 3;
    int cbase = cg * 5;

    float acc[4][5];
#pragma unroll
    for (int j = 0; j < 4; j++)
#pragma unroll
        for (int c = 0; c < 5; c++) acc[j][c] = 0.f;

#pragma unroll 4
    for (int k = 0; k < 256; k++) {
        float wv[5];
#pragma unroll
        for (int c = 0; c < 5; c++) wv[c] = ws[k * 40 + cbase + c];
#pragma unroll
        for (int j = 0; j < 4; j++) {
            float h = hs[(rq * 4 + j) * 257 + k];
            acc[j][0] += h * wv[0];
            acc[j][1] += h * wv[1];
            acc[j][2] += h * wv[2];
            acc[j][3] += h * wv[3];
            acc[j][4] += h * wv[4];
        }
    }

#pragma unroll
    for (int j = 0; j < 4; j++) {
        int gr = r0 + rq * 4 + j;
        if (gr < n) {
#pragma unroll
            for (int c = 0; c < 5; c++)
                out[(size_t)gr * 40 + cbase + c] = acc[j][c] + __ldg(b_out + cbase + c);
        }
    }
}

// ---------------------------------------------------------------------------
static void build_csr_and_gather(const int* ei, int E, const float* feat, int n)
{
    int nb_scan = (n + 1023) / 1024;
    zero_deg_kernel<<<256, 256>>>(n);
    count_kernel<<<(E + 255) / 256, 256>>>(ei, E);
    scan1_kernel<<<nb_scan, 1024>>>(n);
    scan2_kernel<<<1, 1024>>>(nb_scan);
    scan3_kernel<<<(n + 255) / 256, 256>>>(n);
    fill_kernel<<<(E + 255) / 256, 256>>>(ei, E);
    gather_kernel<<<(n * 32 + 255) / 256, 256>>>(feat, n);
}

extern "C" void kernel_launch(void* const* d_in, const int* in_sizes, int n_in,
                              void* d_out, int out_size)
{
    const float* x     = (const float*)d_in[0];
    const int*   ei1   = (const int*)d_in[1];
    const int*   ei2   = (const int*)d_in[2];
    const float* wl1   = (const float*)d_in[3];
    const float* wr1   = (const float*)d_in[4];
    const float* b1    = (const float*)d_in[5];
    const float* wl2   = (const float*)d_in[6];
    const float* wr2   = (const float*)d_in[7];
    const float* b2    = (const float*)d_in[8];
    const float* w_out = (const float*)d_in[9];
    const float* b_out = (const float*)d_in[10];

    int n  = in_sizes[0] / D;
    int E1 = in_sizes[1] / 2;
    int E2 = in_sizes[2] / 2;
    int n_rows_out = out_size / 40;

    void *p_h1 = nullptr, *p_h2 = nullptr;
    cudaGetSymbolAddress(&p_h1, g_h1);
    cudaGetSymbolAddress(&p_h2, g_h2);
    float* h1 = (float*)p_h1;
    float* h2 = (float*)p_h2;

    const int LAYER_SMEM = (2 * 64 + 2 * 128) * APAD * 2;   // 101376 B
    cudaFuncSetAttribute(layer_mma_kernel,
                         cudaFuncAttributeMaxDynamicSharedMemorySize, LAYER_SMEM);
    cudaFuncSetAttribute(out_kernel,
                         cudaFuncAttributeMaxDynamicSharedMemorySize, 172544);

    int layer_blocks = (n + 63) / 64;

    // ---- layer 1 ----
    prep_w_kernel<<<128, 256>>>(wl1, wr1);
    build_csr_and_gather(ei1, E1, x, n);
    layer_mma_kernel<<<layer_blocks, 256, LAYER_SMEM>>>(x, b1, h1, n);

    // ---- layer 2 ----
    prep_w_kernel<<<128, 256>>>(wl2, wr2);
    build_csr_and_gather(ei2, E2, h1, n);
    layer_mma_kernel<<<layer_blocks, 256, LAYER_SMEM>>>(h1, b2, h2, n);

    // ---- JK cat + linear head ----
    out_kernel<<<(n_rows_out + 127) / 128, 256, 172544>>>(
        w_out, b_out, (float*)d_out, n_rows_out);
}